// round 1
// baseline (speedup 1.0000x reference)
#include <cuda_runtime.h>
#include <cuda_bf16.h>
#include <math.h>

// Problem constants
#define TT 20
#define DIN 4
#define HH 768
#define BB 1024
#define G4 (4*HH)        // 3072
#define BE_BSTRIDE (TT*HH)  // 15360
#define BP_BSTRIDE (TT*DIN) // 80

// ---------------- device scratch (static, no runtime alloc) ----------------
__device__ float d_gates0[BB * G4];        // 12 MB
__device__ float d_c[BB * HH];             // 3 MB
__device__ float d_rowsum[TT * G4];
__device__ float d_biassum[TT * G4];
__device__ float d_evsum[TT];
__device__ float d_hsum[TT];

// ---------------- helpers ----------------
__device__ __forceinline__ float fast_sigmoid(float x) {
    // 1/(1+e^-x) via MUFU EX2 + RCP; relative error ~1e-6
    return __fdividef(1.0f, 1.0f + __expf(-x));
}
__device__ __forceinline__ float fast_tanh(float x) {
    // 2/(1+e^-2x) - 1
    return __fdividef(2.0f, 1.0f + __expf(-2.0f * x)) - 1.0f;
}

__device__ __forceinline__ float blockReduce256(float v) {
    __shared__ float red[8];
    int lane = threadIdx.x & 31, wid = threadIdx.x >> 5;
#pragma unroll
    for (int o = 16; o; o >>= 1) v += __shfl_down_sync(0xffffffffu, v, o);
    if (lane == 0) red[wid] = v;
    __syncthreads();
    if (wid == 0) {
        v = (lane < 8) ? red[lane] : 0.0f;
#pragma unroll
        for (int o = 4; o; o >>= 1) v += __shfl_down_sync(0xffffffffu, v, o);
    }
    __syncthreads();   // make helper safely reusable
    return v;          // valid in thread 0
}

// ---------------- kernel 0: zero accumulators ----------------
__global__ void init_kernel() {
    int i = threadIdx.x;
    if (i < TT) { d_evsum[i] = 0.0f; d_hsum[i] = 0.0f; }
}

// ---------------- kernel 1: rowsum(W_hh[t]) + bias sums, t=1..19 ----------
// one warp per (t,j) row; 19*3072 = 58368 rows
__global__ void prep_kernel(const float* __restrict__ whh,
                            const float* __restrict__ bih,
                            const float* __restrict__ bhh) {
    int row = blockIdx.x * 8 + (threadIdx.x >> 5);
    if (row >= 19 * G4) return;
    int t = 1 + row / G4;
    int j = row - (t - 1) * G4;
    const float* p = whh + ((size_t)t * G4 + j) * HH;
    int lane = threadIdx.x & 31;
    float s = 0.0f;
#pragma unroll 6
    for (int k = lane; k < HH; k += 32) s += p[k];
#pragma unroll
    for (int o = 16; o; o >>= 1) s += __shfl_down_sync(0xffffffffu, s, o);
    if (lane == 0) {
        d_rowsum[t * G4 + j]  = s;
        d_biassum[t * G4 + j] = bih[t * G4 + j] + bhh[t * G4 + j];
    }
}

// ---------------- kernel 2: evsum[t] = sum_{b,h} batch_event[b,t,h], t=1..19
__global__ void evsum_kernel(const float* __restrict__ be) {
    int t = 1 + blockIdx.y;           // gridDim.y = 19
    int chunk = blockIdx.x;           // gridDim.x = 16 -> 64 b per block
    float s = 0.0f;
    int b0 = chunk * 64;
    for (int b = b0; b < b0 + 64; b++) {
        const float* p = be + (size_t)b * BE_BSTRIDE + t * HH;
#pragma unroll 3
        for (int h = threadIdx.x; h < HH; h += 256) s += p[h];
    }
    float v = blockReduce256(s);
    if (threadIdx.x == 0) atomicAdd(&d_evsum[t], v);
}

// ---------------- kernel 3: step-0 GEMM ----------------
// gates0[m][n] = sum_k ev0[m,k]*Whh0[n,k] + b_ih0[n]+b_hh0[n] + dot4(x0[m], Wih0[n])
#define BM 128
#define BN 128
#define BKK 8
#define TM 8
#define TN 8
__global__ __launch_bounds__(256) void gemm0_kernel(
        const float* __restrict__ be,  const float* __restrict__ whh,
        const float* __restrict__ bp,  const float* __restrict__ wih,
        const float* __restrict__ bih, const float* __restrict__ bhh) {
    __shared__ __align__(16) float As[BKK][BM];
    __shared__ __align__(16) float Bs[BKK][BN];
    int tid = threadIdx.x;
    int tx = tid & 15, ty = tid >> 4;
    int m0 = blockIdx.y * BM, n0 = blockIdx.x * BN;

    float acc[TM][TN];
#pragma unroll
    for (int i = 0; i < TM; i++)
#pragma unroll
        for (int j = 0; j < TN; j++) acc[i][j] = 0.0f;

    int lm = tid >> 1;
    int lk = (tid & 1) * 4;
    const float* Abase = be  + (size_t)(m0 + lm) * BE_BSTRIDE + lk; // t=0
    const float* Bbase = whh + (size_t)(n0 + lm) * HH + lk;         // t=0

    for (int k0 = 0; k0 < HH; k0 += BKK) {
        float4 a = *(const float4*)(Abase + k0);
        float4 b = *(const float4*)(Bbase + k0);
        As[lk+0][lm] = a.x; As[lk+1][lm] = a.y; As[lk+2][lm] = a.z; As[lk+3][lm] = a.w;
        Bs[lk+0][lm] = b.x; Bs[lk+1][lm] = b.y; Bs[lk+2][lm] = b.z; Bs[lk+3][lm] = b.w;
        __syncthreads();
#pragma unroll
        for (int k = 0; k < BKK; k++) {
            float4 a0 = *(const float4*)&As[k][ty * TM];
            float4 a1 = *(const float4*)&As[k][ty * TM + 4];
            float4 b0 = *(const float4*)&Bs[k][tx * TN];
            float4 b1 = *(const float4*)&Bs[k][tx * TN + 4];
            float ar[TM] = {a0.x,a0.y,a0.z,a0.w,a1.x,a1.y,a1.z,a1.w};
            float br[TN] = {b0.x,b0.y,b0.z,b0.w,b1.x,b1.y,b1.z,b1.w};
#pragma unroll
            for (int i = 0; i < TM; i++)
#pragma unroll
                for (int j = 0; j < TN; j++)
                    acc[i][j] = fmaf(ar[i], br[j], acc[i][j]);
        }
        __syncthreads();
    }

    // epilogue: + biases + x0 . Wih0[n]
    float bb[TN]; float4 w4[TN];
#pragma unroll
    for (int j = 0; j < TN; j++) {
        int n = n0 + tx * TN + j;
        bb[j] = bih[n] + bhh[n];
        w4[j] = ((const float4*)wih)[n];   // Wih[0][n][0..3]
    }
#pragma unroll
    for (int i = 0; i < TM; i++) {
        int m = m0 + ty * TM + i;
        float4 x = ((const float4*)bp)[(size_t)m * TT];  // bp[m][0][0..3]
        float out[TN];
#pragma unroll
        for (int j = 0; j < TN; j++) {
            out[j] = acc[i][j] + bb[j]
                   + x.x * w4[j].x + x.y * w4[j].y + x.z * w4[j].z + x.w * w4[j].w;
        }
        float* dst = &d_gates0[(size_t)m * G4 + n0 + tx * TN];
        *(float4*)(dst)     = make_float4(out[0], out[1], out[2], out[3]);
        *(float4*)(dst + 4) = make_float4(out[4], out[5], out[6], out[7]);
    }
}

// ---------------- kernel 4: step-0 activations -> c0, hsum[0] -------------
__global__ __launch_bounds__(256) void act0_kernel() {
    int b = blockIdx.x;
    const float* g = &d_gates0[(size_t)b * G4];
    float acc = 0.0f;
#pragma unroll
    for (int r = 0; r < 3; r++) {
        int h = threadIdx.x + r * 256;
        float gi = g[h];
        float gg = g[h + 2 * HH];
        float go = g[h + 3 * HH];
        float cn = fast_sigmoid(gi) * fast_tanh(gg);   // c_prev = 0
        d_c[(size_t)b * HH + h] = cn;
        acc += fast_sigmoid(go) * fast_tanh(cn);
    }
    float v = blockReduce256(acc);
    if (threadIdx.x == 0) atomicAdd(&d_hsum[0], v);
}

// ---------------- kernel 5: steps t=1..19 (scalar-h_mat LSTM cell) --------
// smem: Wih[t] as float4[3072] (48KB) + rowsum (12KB) + biassum (12KB) + fcw (3KB)
#define STEP_SMEM ((G4*4 + G4 + G4 + HH) * 4)  // 76800 bytes
__global__ __launch_bounds__(256) void step_kernel(
        const float* __restrict__ bp, const float* __restrict__ wih,
        const float* __restrict__ fcw, const float* __restrict__ fcb,
        float* __restrict__ out, int t, int last) {
    extern __shared__ float sm[];
    float4* s_w4 = (float4*)sm;          // 3072 float4
    float*  s_rs = sm + G4 * 4;          // 3072
    float*  s_bs = s_rs + G4;            // 3072
    float*  s_fw = s_bs + G4;            // 768

    const float* wt = wih + (size_t)t * G4 * DIN;
    const float4* wt4 = (const float4*)wt;
    for (int i = threadIdx.x; i < G4; i += 256) {
        s_w4[i] = wt4[i];
        s_rs[i] = d_rowsum[t * G4 + i];
        s_bs[i] = d_biassum[t * G4 + i];
    }
    if (last) for (int i = threadIdx.x; i < HH; i += 256) s_fw[i] = fcw[i];
    __syncthreads();

    float hx = d_evsum[t] + d_hsum[t - 1];
    float fcbias = last ? fcb[0] : 0.0f;

    int b0 = blockIdx.x * 4;             // gridDim.x = 256 -> 4 batch rows/block
    float hacc = 0.0f;
    for (int bi = 0; bi < 4; bi++) {
        int b = b0 + bi;
        float4 x = *(const float4*)(bp + (size_t)b * BP_BSTRIDE + t * DIN);
        float* crow = &d_c[(size_t)b * HH];
        float bacc = 0.0f;
#pragma unroll
        for (int r = 0; r < 3; r++) {
            int h = threadIdx.x + r * 256;
            // 4 gates: j = h + g*H
            float gi, gf, gg, go;
            {
                int j = h;
                float4 w = s_w4[j];
                gi = fmaf(hx, s_rs[j], s_bs[j]) + x.x*w.x + x.y*w.y + x.z*w.z + x.w*w.w;
            }
            {
                int j = h + HH;
                float4 w = s_w4[j];
                gf = fmaf(hx, s_rs[j], s_bs[j]) + x.x*w.x + x.y*w.y + x.z*w.z + x.w*w.w;
            }
            {
                int j = h + 2*HH;
                float4 w = s_w4[j];
                gg = fmaf(hx, s_rs[j], s_bs[j]) + x.x*w.x + x.y*w.y + x.z*w.z + x.w*w.w;
            }
            {
                int j = h + 3*HH;
                float4 w = s_w4[j];
                go = fmaf(hx, s_rs[j], s_bs[j]) + x.x*w.x + x.y*w.y + x.z*w.z + x.w*w.w;
            }
            float c  = crow[h];
            float cn = fast_sigmoid(gf) * c + fast_sigmoid(gi) * fast_tanh(gg);
            crow[h] = cn;
            float hn = fast_sigmoid(go) * fast_tanh(cn);
            if (last) bacc += hn * s_fw[h];
            else      hacc += hn;
        }
        if (last) {
            float v = blockReduce256(bacc);
            if (threadIdx.x == 0) out[b] = v + fcbias;
        }
    }
    if (!last) {
        float v = blockReduce256(hacc);
        if (threadIdx.x == 0) atomicAdd(&d_hsum[t], v);
    }
}

// ---------------- launcher ----------------
extern "C" void kernel_launch(void* const* d_in, const int* in_sizes, int n_in,
                              void* d_out, int out_size) {
    const float* bp  = (const float*)d_in[0];  // batch_price (1024,20,4)
    const float* be  = (const float*)d_in[1];  // batch_event (1024,20,768)
    const float* wih = (const float*)d_in[2];  // W_ih (20,3072,4)
    const float* whh = (const float*)d_in[3];  // W_hh (20,3072,768)
    const float* bih = (const float*)d_in[4];  // b_ih (20,3072)
    const float* bhh = (const float*)d_in[5];  // b_hh (20,3072)
    const float* fcw = (const float*)d_in[6];  // fc_w (1,768)
    const float* fcb = (const float*)d_in[7];  // fc_b (1,)
    float* out = (float*)d_out;                // (1024,1)

    // step kernel needs >48KB dynamic smem
    cudaFuncSetAttribute(step_kernel,
                         cudaFuncAttributeMaxDynamicSharedMemorySize, STEP_SMEM);

    init_kernel<<<1, 32>>>();
    prep_kernel<<<(19 * G4 + 7) / 8, 256>>>(whh, bih, bhh);
    evsum_kernel<<<dim3(16, 19), 256>>>(be);
    gemm0_kernel<<<dim3(G4 / BN, BB / BM), 256>>>(be, whh, bp, wih, bih, bhh);
    act0_kernel<<<BB, 256>>>();
    for (int t = 1; t < TT; t++) {
        step_kernel<<<BB / 4, 256, STEP_SMEM>>>(bp, wih, fcw, fcb, out, t, t == TT - 1);
    }
}

// round 2
// speedup vs baseline: 1.2854x; 1.2854x over previous
#include <cuda_runtime.h>
#include <cuda_bf16.h>
#include <math.h>
#include <stdint.h>

// Problem constants
#define TT 20
#define DIN 4
#define HH 768
#define BB 1024
#define G4 (4*HH)           // 3072
#define BE_BSTRIDE (TT*HH)  // 15360
#define BP_BSTRIDE (TT*DIN) // 80
#define NBLK 148            // persistent grid (>= co-resident guaranteed)

// ---------------- device scratch ----------------
__device__ float d_ct[HH * BB];            // c state, [h][b] layout, 3 MB
__device__ float d_rowsum[TT * G4];
__device__ float d_biassum[TT * G4];
__device__ float d_evsum[TT];
__device__ float d_hsum[TT];
__device__ unsigned d_barcnt;

// ---------------- helpers ----------------
__device__ __forceinline__ float fast_sigmoid(float x) {
    return __fdividef(1.0f, 1.0f + __expf(-x));
}
__device__ __forceinline__ float fast_tanh(float x) {
    return __fdividef(2.0f, 1.0f + __expf(-2.0f * x)) - 1.0f;
}
__device__ __forceinline__ uint32_t f2tf32(float f) {
    uint32_t r; asm("cvt.rna.tf32.f32 %0, %1;" : "=r"(r) : "f"(f)); return r;
}
__device__ __forceinline__ float blockReduce256(float v) {
    __shared__ float red[8];
    int lane = threadIdx.x & 31, wid = threadIdx.x >> 5;
#pragma unroll
    for (int o = 16; o; o >>= 1) v += __shfl_down_sync(0xffffffffu, v, o);
    if (lane == 0) red[wid] = v;
    __syncthreads();
    if (wid == 0) {
        v = (lane < 8) ? red[lane] : 0.0f;
#pragma unroll
        for (int o = 4; o; o >>= 1) v += __shfl_down_sync(0xffffffffu, v, o);
    }
    __syncthreads();
    return v; // valid in thread 0
}

// grid-wide barrier: monotonic counter, reset by init_kernel each launch
__device__ __forceinline__ void gridbar(unsigned target) {
    __syncthreads();
    if (threadIdx.x == 0) {
        __threadfence();
        atomicAdd(&d_barcnt, 1u);
        while (atomicAdd(&d_barcnt, 0u) < target) __nanosleep(64);
        __threadfence();
    }
    __syncthreads();
}

// ---------------- kernel 0: init ----------------
__global__ void init_kernel(const float* __restrict__ fcb, float* __restrict__ out) {
    int i = threadIdx.x;
    if (i < BB) out[i] = fcb[0];
    if (i < TT) { d_evsum[i] = 0.0f; d_hsum[i] = 0.0f; }
    if (i == 0) d_barcnt = 0u;
}

// ---------------- kernel 1: step-0 GEMM (tf32 mma) + fused activations ----
// D[b, 3 gates x 32 h] = ev0[b,:] @ Whh0[gate_row,:]  then epilogue:
//   gates += bias + x0.Wih0 ; c = sig(i)*tanh(g) -> d_ct[h][b] ; hsum0 += sig(o)*tanh(c)
#define GBM 128     // batch tile
#define GBH 32      // h tile  (-> 96 gate rows: i,g,o)
#define GBN 96
#define GBK 16
#define ASTR 20     // smem strides (padded, conflict-free frag loads)
#define BSTR 20
#define GSTR 132    // epilogue gates buffer stride
#define GEMM_SMEM (GBN * GSTR * 4)  // 50688 B (>= pipeline 35840 B)

__global__ __launch_bounds__(256, 2) void gemm0_kernel(
        const float* __restrict__ be,  const float* __restrict__ whh,
        const float* __restrict__ bp,  const float* __restrict__ wih,
        const float* __restrict__ bih, const float* __restrict__ bhh) {
    extern __shared__ uint32_t sm_u[];
    uint32_t* smA = sm_u;                    // 2 x 128 x 20
    uint32_t* smB = sm_u + 2 * GBM * ASTR;   // 2 x 96 x 20
    float*    gsm = (float*)sm_u;            // epilogue reuse: [96][132]

    const int tid  = threadIdx.x;
    const int lane = tid & 31;
    const int wid  = tid >> 5;
    const int wm   = wid >> 1;   // 0..3
    const int wn   = wid & 1;    // 0..1
    const int r    = lane >> 2;  // 0..7
    const int cl   = lane & 3;   // 0..3
    const int hblk = blockIdx.x; // 0..23
    const int mblk = blockIdx.y; // 0..7
    const int m0   = mblk * GBM;

    // loader thread mapping
    const int arow0 = tid >> 2;          // A: rows 0..63 (+64 second pass)
    const int ac4   = tid & 3;
    const int brow  = tid >> 2;          // B: i=tid -> rows 0..63 ; i=tid+256 -> rows 64..95 (tid<128)
    const int brow2 = (tid + 256) >> 2;
    // gate row mapping for B rows 0..95: [0,32)->i, [32,64)->g, [64,96)->o
    auto growf = [&] (int row) {
        int q = row >> 5;
        int g = (q == 0) ? 0 : (q == 1 ? 2 : 3);
        return g * HH + hblk * GBH + (row & 31);
    };
    const int grow1 = growf(brow);
    const int grow2 = growf(brow2 < GBN ? brow2 : 0);
    const bool bpred2 = (brow2 < GBN);

    float acc[2][6][4];
#pragma unroll
    for (int i = 0; i < 2; i++)
#pragma unroll
        for (int j = 0; j < 6; j++)
#pragma unroll
            for (int q = 0; q < 4; q++) acc[i][j][q] = 0.0f;

    float4 ra[2], rb[2];
    auto ldg = [&](int kt) {
        const float* A0 = be + (size_t)(m0 + arow0) * BE_BSTRIDE + kt * GBK + ac4 * 4;
        const float* A1 = be + (size_t)(m0 + arow0 + 64) * BE_BSTRIDE + kt * GBK + ac4 * 4;
        ra[0] = *(const float4*)A0;
        ra[1] = *(const float4*)A1;
        rb[0] = *(const float4*)(whh + (size_t)grow1 * HH + kt * GBK + ac4 * 4);
        if (bpred2)
            rb[1] = *(const float4*)(whh + (size_t)grow2 * HH + ((tid + 256) & 3) * 4 + kt * GBK);
    };
    auto sts = [&](int buf) {
        uint32_t* pa = smA + buf * (GBM * ASTR);
        uint32_t* pb = smB + buf * (GBN * BSTR);
        uint4 v;
        v.x = f2tf32(ra[0].x); v.y = f2tf32(ra[0].y); v.z = f2tf32(ra[0].z); v.w = f2tf32(ra[0].w);
        *(uint4*)(pa + arow0 * ASTR + ac4 * 4) = v;
        v.x = f2tf32(ra[1].x); v.y = f2tf32(ra[1].y); v.z = f2tf32(ra[1].z); v.w = f2tf32(ra[1].w);
        *(uint4*)(pa + (arow0 + 64) * ASTR + ac4 * 4) = v;
        v.x = f2tf32(rb[0].x); v.y = f2tf32(rb[0].y); v.z = f2tf32(rb[0].z); v.w = f2tf32(rb[0].w);
        *(uint4*)(pb + brow * BSTR + ac4 * 4) = v;
        if (bpred2) {
            v.x = f2tf32(rb[1].x); v.y = f2tf32(rb[1].y); v.z = f2tf32(rb[1].z); v.w = f2tf32(rb[1].w);
            *(uint4*)(pb + brow2 * BSTR + ((tid + 256) & 3) * 4) = v;
        }
    };

    ldg(0);
    sts(0);
    __syncthreads();

    const int NKT = HH / GBK;   // 48
    for (int kt = 0; kt < NKT; kt++) {
        int buf = kt & 1;
        if (kt < NKT - 1) ldg(kt + 1);

        const uint32_t* pa = smA + buf * (GBM * ASTR);
        const uint32_t* pb = smB + buf * (GBN * BSTR);
#pragma unroll
        for (int kk = 0; kk < 2; kk++) {
            const int kof = kk * 8;
            uint32_t af[2][4], bf[6][2];
#pragma unroll
            for (int i = 0; i < 2; i++) {
                int m = wm * 32 + i * 16 + r;
                af[i][0] = pa[m * ASTR + kof + cl];
                af[i][1] = pa[(m + 8) * ASTR + kof + cl];
                af[i][2] = pa[m * ASTR + kof + cl + 4];
                af[i][3] = pa[(m + 8) * ASTR + kof + cl + 4];
            }
#pragma unroll
            for (int j = 0; j < 6; j++) {
                int n = wn * 48 + j * 8 + r;
                bf[j][0] = pb[n * BSTR + kof + cl];
                bf[j][1] = pb[n * BSTR + kof + cl + 4];
            }
#pragma unroll
            for (int i = 0; i < 2; i++)
#pragma unroll
                for (int j = 0; j < 6; j++) {
                    asm volatile(
                        "mma.sync.aligned.m16n8k8.row.col.f32.tf32.tf32.f32 "
                        "{%0,%1,%2,%3}, {%4,%5,%6,%7}, {%8,%9}, {%0,%1,%2,%3};"
                        : "+f"(acc[i][j][0]), "+f"(acc[i][j][1]),
                          "+f"(acc[i][j][2]), "+f"(acc[i][j][3])
                        : "r"(af[i][0]), "r"(af[i][1]), "r"(af[i][2]), "r"(af[i][3]),
                          "r"(bf[j][0]), "r"(bf[j][1]));
                }
        }
        if (kt < NKT - 1) {
            sts(buf ^ 1);
            __syncthreads();
        }
    }

    // epilogue: dump accumulators to smem [n][m], then fused activations
    __syncthreads();
#pragma unroll
    for (int i = 0; i < 2; i++)
#pragma unroll
        for (int j = 0; j < 6; j++) {
            int m = wm * 32 + i * 16 + r;
            int n = wn * 48 + j * 8 + 2 * cl;
            gsm[n * GSTR + m]           = acc[i][j][0];
            gsm[(n + 1) * GSTR + m]     = acc[i][j][1];
            gsm[n * GSTR + m + 8]       = acc[i][j][2];
            gsm[(n + 1) * GSTR + m + 8] = acc[i][j][3];
        }
    __syncthreads();

    const int m = tid & 127;
    const int b = m0 + m;
    const float4 x = *(const float4*)(bp + (size_t)b * BP_BSTRIDE);  // t=0
    float hpart = 0.0f;
#pragma unroll
    for (int it = 0; it < 16; it++) {
        int hl = (tid >> 7) + it * 2;        // 0..31
        int hg = hblk * GBH + hl;            // global h
        int ri = hg, rg = 2 * HH + hg, ro = 3 * HH + hg;
        float4 wi = ((const float4*)wih)[ri];
        float4 wg = ((const float4*)wih)[rg];
        float4 wo = ((const float4*)wih)[ro];
        float gi = gsm[hl * GSTR + m]        + bih[ri] + bhh[ri]
                 + x.x * wi.x + x.y * wi.y + x.z * wi.z + x.w * wi.w;
        float gg = gsm[(hl + 32) * GSTR + m] + bih[rg] + bhh[rg]
                 + x.x * wg.x + x.y * wg.y + x.z * wg.z + x.w * wg.w;
        float go = gsm[(hl + 64) * GSTR + m] + bih[ro] + bhh[ro]
                 + x.x * wo.x + x.y * wo.y + x.z * wo.z + x.w * wo.w;
        float cn = fast_sigmoid(gi) * fast_tanh(gg);     // c_prev = 0, f-gate dead
        d_ct[(size_t)hg * BB + b] = cn;
        hpart += fast_sigmoid(go) * fast_tanh(cn);
    }
    float v = blockReduce256(hpart);
    if (tid == 0) atomicAdd(&d_hsum[0], v);
}

// ---------------- kernel 2: persistent prep + 19 steps ----------------
__global__ __launch_bounds__(256) void persist_kernel(
        const float* __restrict__ bp,  const float* __restrict__ be,
        const float* __restrict__ whh, const float* __restrict__ wih,
        const float* __restrict__ bih, const float* __restrict__ bhh,
        const float* __restrict__ fcw, float* __restrict__ out) {
    const int tid  = threadIdx.x;
    const int bid  = blockIdx.x;
    const int lane = tid & 31;
    const int gw   = bid * 8 + (tid >> 5);   // global warp id (0..NBLK*8)
    unsigned epoch = 0;

    // --- phase A: rowsum(W_hh[t]) + biassum, t=1..19 ---
    for (int row = gw; row < 19 * G4; row += NBLK * 8) {
        int t = 1 + row / G4;
        int j = row - (t - 1) * G4;
        const float* p = whh + ((size_t)t * G4 + j) * HH;
        float s = 0.0f;
#pragma unroll 6
        for (int k = lane; k < HH; k += 32) s += p[k];
#pragma unroll
        for (int o = 16; o; o >>= 1) s += __shfl_down_sync(0xffffffffu, s, o);
        if (lane == 0) {
            d_rowsum[t * G4 + j]  = s;
            d_biassum[t * G4 + j] = bih[t * G4 + j] + bhh[t * G4 + j];
        }
    }
    // --- phase B: evsum[t], t=1..19 ---
    for (int row = gw; row < 19 * BB; row += NBLK * 8) {
        int t = 1 + (row >> 10);
        int b = row & (BB - 1);
        const float* p = be + (size_t)b * BE_BSTRIDE + t * HH;
        float s = 0.0f;
#pragma unroll 6
        for (int k = lane; k < HH; k += 32) s += p[k];
#pragma unroll
        for (int o = 16; o; o >>= 1) s += __shfl_down_sync(0xffffffffu, s, o);
        if (lane == 0) atomicAdd(&d_evsum[t], s);
    }
    gridbar(++epoch * NBLK);

    // --- phase C: 19 recurrent steps, block owns h-slice {bid, bid+148, ...} ---
    float fcacc[4] = {0.f, 0.f, 0.f, 0.f};
    const float4* wih4 = (const float4*)wih;

    for (int t = 1; t < TT; t++) {
        const float hx = d_evsum[t] + d_hsum[t - 1];
        const int last = (t == TT - 1);
        float hacc = 0.0f;

        float4 x[4];
#pragma unroll
        for (int k = 0; k < 4; k++)
            x[k] = *(const float4*)(bp + (size_t)(tid + (k << 8)) * BP_BSTRIDE + t * DIN);

        for (int h = bid; h < HH; h += NBLK) {
            const int base = t * G4;
            float4 w0 = wih4[base + h];
            float4 w1 = wih4[base + HH + h];
            float4 w2 = wih4[base + 2 * HH + h];
            float4 w3 = wih4[base + 3 * HH + h];
            float pre0 = fmaf(hx, d_rowsum[base + h],          d_biassum[base + h]);
            float pre1 = fmaf(hx, d_rowsum[base + HH + h],     d_biassum[base + HH + h]);
            float pre2 = fmaf(hx, d_rowsum[base + 2 * HH + h], d_biassum[base + 2 * HH + h]);
            float pre3 = fmaf(hx, d_rowsum[base + 3 * HH + h], d_biassum[base + 3 * HH + h]);
            float fw = last ? fcw[h] : 0.0f;
            float* crow = d_ct + (size_t)h * BB;
#pragma unroll
            for (int k = 0; k < 4; k++) {
                int b = tid + (k << 8);
                float gi = pre0 + x[k].x * w0.x + x[k].y * w0.y + x[k].z * w0.z + x[k].w * w0.w;
                float gf = pre1 + x[k].x * w1.x + x[k].y * w1.y + x[k].z * w1.z + x[k].w * w1.w;
                float gg = pre2 + x[k].x * w2.x + x[k].y * w2.y + x[k].z * w2.z + x[k].w * w2.w;
                float go = pre3 + x[k].x * w3.x + x[k].y * w3.y + x[k].z * w3.z + x[k].w * w3.w;
                float c  = crow[b];
                float cn = fast_sigmoid(gf) * c + fast_sigmoid(gi) * fast_tanh(gg);
                crow[b] = cn;
                float hn = fast_sigmoid(go) * fast_tanh(cn);
                if (last) fcacc[k] += hn * fw;
                else      hacc += hn;
            }
        }
        if (!last) {
            float v = blockReduce256(hacc);
            if (tid == 0) atomicAdd(&d_hsum[t], v);
            gridbar(++epoch * NBLK);
        }
    }
    // final FC accumulation (out pre-initialized to fc_b by init_kernel)
#pragma unroll
    for (int k = 0; k < 4; k++)
        atomicAdd(&out[tid + (k << 8)], fcacc[k]);
}

// ---------------- launcher ----------------
extern "C" void kernel_launch(void* const* d_in, const int* in_sizes, int n_in,
                              void* d_out, int out_size) {
    const float* bp  = (const float*)d_in[0];  // batch_price (1024,20,4)
    const float* be  = (const float*)d_in[1];  // batch_event (1024,20,768)
    const float* wih = (const float*)d_in[2];  // W_ih (20,3072,4)
    const float* whh = (const float*)d_in[3];  // W_hh (20,3072,768)
    const float* bih = (const float*)d_in[4];  // b_ih (20,3072)
    const float* bhh = (const float*)d_in[5];  // b_hh (20,3072)
    const float* fcw = (const float*)d_in[6];  // fc_w (1,768)
    const float* fcb = (const float*)d_in[7];  // fc_b (1,)
    float* out = (float*)d_out;                // (1024,1)

    cudaFuncSetAttribute(gemm0_kernel,
                         cudaFuncAttributeMaxDynamicSharedMemorySize, GEMM_SMEM);

    init_kernel<<<1, 1024>>>(fcb, out);
    gemm0_kernel<<<dim3(HH / GBH, BB / GBM), 256, GEMM_SMEM>>>(be, whh, bp, wih, bih, bhh);
    persist_kernel<<<NBLK, 256>>>(bp, be, whh, wih, bih, bhh, fcw, out);
}

// round 3
// speedup vs baseline: 1.4792x; 1.1508x over previous
#include <cuda_runtime.h>
#include <cuda_bf16.h>
#include <math.h>
#include <stdint.h>

// Problem constants
#define TT 20
#define DIN 4
#define HH 768
#define BB 1024
#define G4 (4*HH)           // 3072
#define BE_BSTRIDE (TT*HH)  // 15360
#define BP_BSTRIDE (TT*DIN) // 80
#define NBLK 148
#define NWARP (NBLK*8)      // 1184

// ---------------- device scratch ----------------
__device__ float d_ct[HH * BB];            // c state, [h][b], 3 MB
__device__ float d_rowsum[TT * G4];
__device__ float d_biassum[TT * G4];
__device__ float d_evsum[TT];
__device__ float d_hsum[TT];
__device__ unsigned d_barcnt;              // zero-init; self-reset at end of launch
__device__ unsigned d_done;

// ---------------- helpers ----------------
__device__ __forceinline__ float fast_sigmoid(float x) {
    return __fdividef(1.0f, 1.0f + __expf(-x));
}
__device__ __forceinline__ float fast_tanh(float x) {
    return __fdividef(2.0f, 1.0f + __expf(-2.0f * x)) - 1.0f;
}
__device__ __forceinline__ uint32_t f2tf32(float f) {
    uint32_t r; asm("cvt.rna.tf32.f32 %0, %1;" : "=r"(r) : "f"(f)); return r;
}
__device__ __forceinline__ float blockReduce256(float v) {
    __shared__ float red[8];
    int lane = threadIdx.x & 31, wid = threadIdx.x >> 5;
#pragma unroll
    for (int o = 16; o; o >>= 1) v += __shfl_down_sync(0xffffffffu, v, o);
    if (lane == 0) red[wid] = v;
    __syncthreads();
    if (wid == 0) {
        v = (lane < 8) ? red[lane] : 0.0f;
#pragma unroll
        for (int o = 4; o; o >>= 1) v += __shfl_down_sync(0xffffffffu, v, o);
    }
    __syncthreads();
    return v; // valid in thread 0
}

__device__ __forceinline__ void gridbar(unsigned target) {
    __syncthreads();
    if (threadIdx.x == 0) {
        __threadfence();
        atomicAdd(&d_barcnt, 1u);
        while (atomicAdd(&d_barcnt, 0u) < target) __nanosleep(64);
        __threadfence();
    }
    __syncthreads();
}

__device__ __forceinline__ float sum6f4(const float4 a[6]) {
    float s = 0.0f;
#pragma unroll
    for (int i = 0; i < 6; i++) s += (a[i].x + a[i].y) + (a[i].z + a[i].w);
    return s;
}
__device__ __forceinline__ float warpsum(float s) {
#pragma unroll
    for (int o = 16; o; o >>= 1) s += __shfl_down_sync(0xffffffffu, s, o);
    return s;
}

// ---------------- GEMM tile (tf32 mma), step 0, fused activations ----------
#define GBM 128
#define GBH 32
#define GBN 96
#define GBK 16
#define ASTR 20
#define BSTR 20
#define GSTR 132
#define FUSED_SMEM (GBN * GSTR * 4)   // 50688 B

__device__ __forceinline__ void gemm_tile(
        int hblk, int mblk,
        const float* __restrict__ be,  const float* __restrict__ whh,
        const float* __restrict__ bp,  const float* __restrict__ wih,
        const float* __restrict__ bih, const float* __restrict__ bhh,
        uint32_t* sm_u) {
    uint32_t* smA = sm_u;
    uint32_t* smB = sm_u + 2 * GBM * ASTR;
    float*    gsm = (float*)sm_u;

    const int tid  = threadIdx.x;
    const int lane = tid & 31;
    const int wid  = tid >> 5;
    const int wm   = wid >> 1;
    const int wn   = wid & 1;
    const int r    = lane >> 2;
    const int cl   = lane & 3;
    const int m0   = mblk * GBM;

    const int arow0 = tid >> 2;
    const int ac4   = tid & 3;
    const int brow  = tid >> 2;
    const int brow2 = (tid + 256) >> 2;
    auto growf = [&] (int row) {
        int q = row >> 5;
        int g = (q == 0) ? 0 : (q == 1 ? 2 : 3);
        return g * HH + hblk * GBH + (row & 31);
    };
    const int grow1 = growf(brow);
    const int grow2 = growf(brow2 < GBN ? brow2 : 0);
    const bool bpred2 = (brow2 < GBN);

    float acc[2][6][4];
#pragma unroll
    for (int i = 0; i < 2; i++)
#pragma unroll
        for (int j = 0; j < 6; j++)
#pragma unroll
            for (int q = 0; q < 4; q++) acc[i][j][q] = 0.0f;

    float4 ra[2], rb[2];
    auto ldg = [&](int kt) {
        ra[0] = *(const float4*)(be + (size_t)(m0 + arow0) * BE_BSTRIDE + kt * GBK + ac4 * 4);
        ra[1] = *(const float4*)(be + (size_t)(m0 + arow0 + 64) * BE_BSTRIDE + kt * GBK + ac4 * 4);
        rb[0] = *(const float4*)(whh + (size_t)grow1 * HH + kt * GBK + ac4 * 4);
        if (bpred2)
            rb[1] = *(const float4*)(whh + (size_t)grow2 * HH + kt * GBK + ac4 * 4);
    };
    auto sts = [&](int buf) {
        uint32_t* pa = smA + buf * (GBM * ASTR);
        uint32_t* pb = smB + buf * (GBN * BSTR);
        uint4 v;
        v.x = f2tf32(ra[0].x); v.y = f2tf32(ra[0].y); v.z = f2tf32(ra[0].z); v.w = f2tf32(ra[0].w);
        *(uint4*)(pa + arow0 * ASTR + ac4 * 4) = v;
        v.x = f2tf32(ra[1].x); v.y = f2tf32(ra[1].y); v.z = f2tf32(ra[1].z); v.w = f2tf32(ra[1].w);
        *(uint4*)(pa + (arow0 + 64) * ASTR + ac4 * 4) = v;
        v.x = f2tf32(rb[0].x); v.y = f2tf32(rb[0].y); v.z = f2tf32(rb[0].z); v.w = f2tf32(rb[0].w);
        *(uint4*)(pb + brow * BSTR + ac4 * 4) = v;
        if (bpred2) {
            v.x = f2tf32(rb[1].x); v.y = f2tf32(rb[1].y); v.z = f2tf32(rb[1].z); v.w = f2tf32(rb[1].w);
            *(uint4*)(pb + brow2 * BSTR + ac4 * 4) = v;
        }
    };

    ldg(0);
    sts(0);
    __syncthreads();

    const int NKT = HH / GBK;   // 48
    for (int kt = 0; kt < NKT; kt++) {
        int buf = kt & 1;
        if (kt < NKT - 1) ldg(kt + 1);

        const uint32_t* pa = smA + buf * (GBM * ASTR);
        const uint32_t* pb = smB + buf * (GBN * BSTR);
#pragma unroll
        for (int kk = 0; kk < 2; kk++) {
            const int kof = kk * 8;
            uint32_t af[2][4], bf[6][2];
#pragma unroll
            for (int i = 0; i < 2; i++) {
                int m = wm * 32 + i * 16 + r;
                af[i][0] = pa[m * ASTR + kof + cl];
                af[i][1] = pa[(m + 8) * ASTR + kof + cl];
                af[i][2] = pa[m * ASTR + kof + cl + 4];
                af[i][3] = pa[(m + 8) * ASTR + kof + cl + 4];
            }
#pragma unroll
            for (int j = 0; j < 6; j++) {
                int n = wn * 48 + j * 8 + r;
                bf[j][0] = pb[n * BSTR + kof + cl];
                bf[j][1] = pb[n * BSTR + kof + cl + 4];
            }
#pragma unroll
            for (int i = 0; i < 2; i++)
#pragma unroll
                for (int j = 0; j < 6; j++) {
                    asm volatile(
                        "mma.sync.aligned.m16n8k8.row.col.f32.tf32.tf32.f32 "
                        "{%0,%1,%2,%3}, {%4,%5,%6,%7}, {%8,%9}, {%0,%1,%2,%3};"
                        : "+f"(acc[i][j][0]), "+f"(acc[i][j][1]),
                          "+f"(acc[i][j][2]), "+f"(acc[i][j][3])
                        : "r"(af[i][0]), "r"(af[i][1]), "r"(af[i][2]), "r"(af[i][3]),
                          "r"(bf[j][0]), "r"(bf[j][1]));
                }
        }
        if (kt < NKT - 1) {
            sts(buf ^ 1);
            __syncthreads();
        }
    }

    __syncthreads();
#pragma unroll
    for (int i = 0; i < 2; i++)
#pragma unroll
        for (int j = 0; j < 6; j++) {
            int m = wm * 32 + i * 16 + r;
            int n = wn * 48 + j * 8 + 2 * cl;
            gsm[n * GSTR + m]           = acc[i][j][0];
            gsm[(n + 1) * GSTR + m]     = acc[i][j][1];
            gsm[n * GSTR + m + 8]       = acc[i][j][2];
            gsm[(n + 1) * GSTR + m + 8] = acc[i][j][3];
        }
    __syncthreads();

    const int m = tid & 127;
    const int b = m0 + m;
    const float4 x = *(const float4*)(bp + (size_t)b * BP_BSTRIDE);  // t=0
    float hpart = 0.0f;
#pragma unroll
    for (int it = 0; it < 16; it++) {
        int hl = (tid >> 7) + it * 2;
        int hg = hblk * GBH + hl;
        int ri = hg, rg = 2 * HH + hg, ro = 3 * HH + hg;
        float4 wi = ((const float4*)wih)[ri];
        float4 wg = ((const float4*)wih)[rg];
        float4 wo = ((const float4*)wih)[ro];
        float gi = gsm[hl * GSTR + m]        + bih[ri] + bhh[ri]
                 + x.x * wi.x + x.y * wi.y + x.z * wi.z + x.w * wi.w;
        float gg = gsm[(hl + 32) * GSTR + m] + bih[rg] + bhh[rg]
                 + x.x * wg.x + x.y * wg.y + x.z * wg.z + x.w * wg.w;
        float go = gsm[(hl + 64) * GSTR + m] + bih[ro] + bhh[ro]
                 + x.x * wo.x + x.y * wo.y + x.z * wo.z + x.w * wo.w;
        float cn = fast_sigmoid(gi) * fast_tanh(gg);   // c_prev = 0, f-gate dead
        d_ct[(size_t)hg * BB + b] = cn;
        hpart += fast_sigmoid(go) * fast_tanh(cn);
    }
    float v = blockReduce256(hpart);
    if (tid == 0) atomicAdd(&d_hsum[0], v);
}

// ---------------- the single fused persistent kernel ----------------
__global__ __launch_bounds__(256, 1) void fused_kernel(
        const float* __restrict__ bp,  const float* __restrict__ be,
        const float* __restrict__ wih, const float* __restrict__ whh,
        const float* __restrict__ bih, const float* __restrict__ bhh,
        const float* __restrict__ fcw, const float* __restrict__ fcb,
        float* __restrict__ out) {
    extern __shared__ uint32_t sm_u[];
    const int tid  = threadIdx.x;
    const int bid  = blockIdx.x;
    const int lane = tid & 31;
    const int gw   = bid * 8 + (tid >> 5);
    unsigned epoch = 0;

    // ---- phase G: step-0 GEMM tiles (192 tiles over 148 blocks) ----
    for (int tile = bid; tile < 192; tile += NBLK) {
        gemm_tile(tile % 24, tile / 24, be, whh, bp, wih, bih, bhh, sm_u);
    }

    // ---- phase A: rowsum(W_hh[t]) + biassum, t=1..19 (float4, 2-row) ----
    for (int r0 = gw; r0 < 19 * G4; r0 += 2 * NWARP) {
        int r1 = r0 + NWARP;
        bool has2 = (r1 < 19 * G4);
        const float4* p0 = (const float4*)(whh + (size_t)(G4 + r0) * HH);
        const float4* p1 = (const float4*)(whh + (size_t)(G4 + (has2 ? r1 : r0)) * HH);
        float4 a[6], b[6];
#pragma unroll
        for (int i = 0; i < 6; i++) a[i] = p0[lane + 32 * i];
        if (has2) {
#pragma unroll
            for (int i = 0; i < 6; i++) b[i] = p1[lane + 32 * i];
        }
        float s0 = warpsum(sum6f4(a));
        float s1 = has2 ? warpsum(sum6f4(b)) : 0.0f;
        if (lane == 0) {
            d_rowsum[G4 + r0]  = s0;
            d_biassum[G4 + r0] = bih[G4 + r0] + bhh[G4 + r0];
            if (has2) {
                d_rowsum[G4 + r1]  = s1;
                d_biassum[G4 + r1] = bih[G4 + r1] + bhh[G4 + r1];
            }
        }
    }

    // ---- phase B: evsum[t] = sum_{b,h} be[b,t,:], t=1..19 (float4, 2-row) ----
    for (int r0 = gw; r0 < 19 * BB; r0 += 2 * NWARP) {
        int r1 = r0 + NWARP;
        bool has2 = (r1 < 19 * BB);
        int t0 = 1 + (r0 >> 10), b0 = r0 & (BB - 1);
        int t1 = 1 + ((has2 ? r1 : r0) >> 10), b1 = (has2 ? r1 : r0) & (BB - 1);
        const float4* p0 = (const float4*)(be + (size_t)b0 * BE_BSTRIDE + t0 * HH);
        const float4* p1 = (const float4*)(be + (size_t)b1 * BE_BSTRIDE + t1 * HH);
        float4 a[6], b[6];
#pragma unroll
        for (int i = 0; i < 6; i++) a[i] = p0[lane + 32 * i];
        if (has2) {
#pragma unroll
            for (int i = 0; i < 6; i++) b[i] = p1[lane + 32 * i];
        }
        float s0 = warpsum(sum6f4(a));
        float s1 = has2 ? warpsum(sum6f4(b)) : 0.0f;
        if (lane == 0) {
            atomicAdd(&d_evsum[t0], s0);
            if (has2) atomicAdd(&d_evsum[t1], s1);
        }
    }

    // out = fc_b (before barrier; all adds to out happen after step 19)
    if (bid == 0) {
        float fb = fcb[0];
        for (int i = tid; i < BB; i += 256) out[i] = fb;
    }

    gridbar(++epoch * NBLK);

    // ---- phase C: 19 recurrent steps; unit = (h, half-of-batch) ----
    const int half  = bid & 1;            // constant across this block's units
    const int bb0   = (half << 9) + tid;  // k=0 batch index
    const float4* wih4 = (const float4*)wih;
    float fcacc0 = 0.0f, fcacc1 = 0.0f;

    for (int t = 1; t < TT; t++) {
        const float hx = d_evsum[t] + d_hsum[t - 1];
        const int last = (t == TT - 1);
        float hacc = 0.0f;

        float4 x0 = *(const float4*)(bp + (size_t)bb0 * BP_BSTRIDE + t * DIN);
        float4 x1 = *(const float4*)(bp + (size_t)(bb0 + 256) * BP_BSTRIDE + t * DIN);

        const int base = t * G4;
        for (int u = bid; u < 2 * HH; u += NBLK) {
            int h = u >> 1;
            float4 w0 = wih4[base + h];
            float4 w1 = wih4[base + HH + h];
            float4 w2 = wih4[base + 2 * HH + h];
            float4 w3 = wih4[base + 3 * HH + h];
            float pre0 = fmaf(hx, d_rowsum[base + h],          d_biassum[base + h]);
            float pre1 = fmaf(hx, d_rowsum[base + HH + h],     d_biassum[base + HH + h]);
            float pre2 = fmaf(hx, d_rowsum[base + 2 * HH + h], d_biassum[base + 2 * HH + h]);
            float pre3 = fmaf(hx, d_rowsum[base + 3 * HH + h], d_biassum[base + 3 * HH + h]);
            float fw = last ? fcw[h] : 0.0f;
            float* crow = d_ct + (size_t)h * BB + (half << 9);

            // k = 0
            {
                float gi = pre0 + x0.x * w0.x + x0.y * w0.y + x0.z * w0.z + x0.w * w0.w;
                float gf = pre1 + x0.x * w1.x + x0.y * w1.y + x0.z * w1.z + x0.w * w1.w;
                float gg = pre2 + x0.x * w2.x + x0.y * w2.y + x0.z * w2.z + x0.w * w2.w;
                float go = pre3 + x0.x * w3.x + x0.y * w3.y + x0.z * w3.z + x0.w * w3.w;
                float c  = crow[tid];
                float cn = fast_sigmoid(gf) * c + fast_sigmoid(gi) * fast_tanh(gg);
                crow[tid] = cn;
                float hn = fast_sigmoid(go) * fast_tanh(cn);
                if (last) fcacc0 += hn * fw; else hacc += hn;
            }
            // k = 1
            {
                float gi = pre0 + x1.x * w0.x + x1.y * w0.y + x1.z * w0.z + x1.w * w0.w;
                float gf = pre1 + x1.x * w1.x + x1.y * w1.y + x1.z * w1.z + x1.w * w1.w;
                float gg = pre2 + x1.x * w2.x + x1.y * w2.y + x1.z * w2.z + x1.w * w2.w;
                float go = pre3 + x1.x * w3.x + x1.y * w3.y + x1.z * w3.z + x1.w * w3.w;
                float c  = crow[tid + 256];
                float cn = fast_sigmoid(gf) * c + fast_sigmoid(gi) * fast_tanh(gg);
                crow[tid + 256] = cn;
                float hn = fast_sigmoid(go) * fast_tanh(cn);
                if (last) fcacc1 += hn * fw; else hacc += hn;
            }
        }
        if (!last) {
            float v = blockReduce256(hacc);
            if (tid == 0) atomicAdd(&d_hsum[t], v);
            gridbar(++epoch * NBLK);
        }
    }

    // final FC accumulation
    atomicAdd(&out[bb0],       fcacc0);
    atomicAdd(&out[bb0 + 256], fcacc1);

    // ---- end-of-launch self-reset (last block to finish cleans state) ----
    __syncthreads();
    if (tid == 0) {
        __threadfence();
        unsigned v = atomicAdd(&d_done, 1u);
        if (v == NBLK - 1) {
            d_barcnt = 0u;
            d_done   = 0u;
#pragma unroll
            for (int i = 0; i < TT; i++) { d_evsum[i] = 0.0f; d_hsum[i] = 0.0f; }
            __threadfence();
        }
    }
}

// ---------------- launcher ----------------
extern "C" void kernel_launch(void* const* d_in, const int* in_sizes, int n_in,
                              void* d_out, int out_size) {
    const float* bp  = (const float*)d_in[0];
    const float* be  = (const float*)d_in[1];
    const float* wih = (const float*)d_in[2];
    const float* whh = (const float*)d_in[3];
    const float* bih = (const float*)d_in[4];
    const float* bhh = (const float*)d_in[5];
    const float* fcw = (const float*)d_in[6];
    const float* fcb = (const float*)d_in[7];
    float* out = (float*)d_out;

    cudaFuncSetAttribute(fused_kernel,
                         cudaFuncAttributeMaxDynamicSharedMemorySize, FUSED_SMEM);

    fused_kernel<<<NBLK, 256, FUSED_SMEM>>>(bp, be, wih, whh, bih, bhh, fcw, fcb, out);
}

// round 4
// speedup vs baseline: 2.2956x; 1.5519x over previous
#include <cuda_runtime.h>
#include <cuda_bf16.h>
#include <math.h>
#include <stdint.h>

// Problem constants
#define TT 20
#define DIN 4
#define HH 768
#define BB 1024
#define G4 (4*HH)           // 3072
#define BE_BSTRIDE (TT*HH)  // 15360
#define BP_BSTRIDE (TT*DIN) // 80
#define NBLK 296            // 2 blocks/SM x 148 SMs, all co-resident
#define NRS   (19*G4)       // rowsum items: 58368
#define NPREP (NRS + 19*BB) // + evsum items: 77824

// ---------------- device scratch ----------------
__device__ float d_ct[HH * BB];            // c state, [h][b], 3 MB
__device__ float d_rowsum[TT * G4];
__device__ float d_biassum[TT * G4];
__device__ float d_evsum[TT];
__device__ float d_hsum[TT];
__device__ unsigned d_barcnt;              // zero-init; self-reset at end
__device__ unsigned d_pctr;                // prep work-steal counter
__device__ unsigned d_done;

// ---------------- helpers ----------------
__device__ __forceinline__ float fast_sigmoid(float x) {
    return __fdividef(1.0f, 1.0f + __expf(-x));
}
__device__ __forceinline__ float fast_tanh(float x) {
    return __fdividef(2.0f, 1.0f + __expf(-2.0f * x)) - 1.0f;
}
__device__ __forceinline__ uint32_t f2tf32(float f) {
    uint32_t r; asm("cvt.rna.tf32.f32 %0, %1;" : "=r"(r) : "f"(f)); return r;
}
__device__ __forceinline__ float blockReduce256(float v) {
    __shared__ float red[8];
    int lane = threadIdx.x & 31, wid = threadIdx.x >> 5;
#pragma unroll
    for (int o = 16; o; o >>= 1) v += __shfl_down_sync(0xffffffffu, v, o);
    if (lane == 0) red[wid] = v;
    __syncthreads();
    if (wid == 0) {
        v = (lane < 8) ? red[lane] : 0.0f;
#pragma unroll
        for (int o = 4; o; o >>= 1) v += __shfl_down_sync(0xffffffffu, v, o);
    }
    __syncthreads();
    return v; // valid in thread 0
}
__device__ __forceinline__ void gridbar(unsigned target) {
    __syncthreads();
    if (threadIdx.x == 0) {
        __threadfence();
        atomicAdd(&d_barcnt, 1u);
        volatile unsigned* p = &d_barcnt;
        while (*p < target) __nanosleep(32);
        __threadfence();
    }
    __syncthreads();
}
__device__ __forceinline__ float sum6f4(const float4 a[6]) {
    float s = 0.0f;
#pragma unroll
    for (int i = 0; i < 6; i++) s += (a[i].x + a[i].y) + (a[i].z + a[i].w);
    return s;
}
__device__ __forceinline__ float warpsum(float s) {
#pragma unroll
    for (int o = 16; o; o >>= 1) s += __shfl_down_sync(0xffffffffu, s, o);
    return s;
}

// ---------------- GEMM tile (tf32 mma), step 0, fused activations ----------
#define GBM 128
#define GBH 32
#define GBN 96
#define GBK 16
#define ASTR 20
#define BSTR 20
#define GSTR 132
#define FUSED_SMEM (GBN * GSTR * 4)   // 50688 B dynamic

__device__ __forceinline__ void gemm_tile(
        int hblk, int mblk,
        const float* __restrict__ be,  const float* __restrict__ whh,
        const float* __restrict__ bp,  const float* __restrict__ wih,
        const float* __restrict__ bih, const float* __restrict__ bhh,
        uint32_t* sm_u) {
    uint32_t* smA = sm_u;
    uint32_t* smB = sm_u + 2 * GBM * ASTR;
    float*    gsm = (float*)sm_u;

    const int tid  = threadIdx.x;
    const int lane = tid & 31;
    const int wid  = tid >> 5;
    const int wm   = wid >> 1;
    const int wn   = wid & 1;
    const int r    = lane >> 2;
    const int cl   = lane & 3;
    const int m0   = mblk * GBM;

    const int arow0 = tid >> 2;
    const int ac4   = tid & 3;
    const int brow  = tid >> 2;
    const int brow2 = (tid + 256) >> 2;
    auto growf = [&] (int row) {
        int q = row >> 5;
        int g = (q == 0) ? 0 : (q == 1 ? 2 : 3);
        return g * HH + hblk * GBH + (row & 31);
    };
    const int grow1 = growf(brow);
    const int grow2 = growf(brow2 < GBN ? brow2 : 0);
    const bool bpred2 = (brow2 < GBN);

    float acc[2][6][4];
#pragma unroll
    for (int i = 0; i < 2; i++)
#pragma unroll
        for (int j = 0; j < 6; j++)
#pragma unroll
            for (int q = 0; q < 4; q++) acc[i][j][q] = 0.0f;

    float4 ra[2], rb[2];
    auto ldg = [&](int kt) {
        ra[0] = *(const float4*)(be + (size_t)(m0 + arow0) * BE_BSTRIDE + kt * GBK + ac4 * 4);
        ra[1] = *(const float4*)(be + (size_t)(m0 + arow0 + 64) * BE_BSTRIDE + kt * GBK + ac4 * 4);
        rb[0] = *(const float4*)(whh + (size_t)grow1 * HH + kt * GBK + ac4 * 4);
        if (bpred2)
            rb[1] = *(const float4*)(whh + (size_t)grow2 * HH + kt * GBK + ac4 * 4);
    };
    auto sts = [&](int buf) {
        uint32_t* pa = smA + buf * (GBM * ASTR);
        uint32_t* pb = smB + buf * (GBN * BSTR);
        uint4 v;
        v.x = f2tf32(ra[0].x); v.y = f2tf32(ra[0].y); v.z = f2tf32(ra[0].z); v.w = f2tf32(ra[0].w);
        *(uint4*)(pa + arow0 * ASTR + ac4 * 4) = v;
        v.x = f2tf32(ra[1].x); v.y = f2tf32(ra[1].y); v.z = f2tf32(ra[1].z); v.w = f2tf32(ra[1].w);
        *(uint4*)(pa + (arow0 + 64) * ASTR + ac4 * 4) = v;
        v.x = f2tf32(rb[0].x); v.y = f2tf32(rb[0].y); v.z = f2tf32(rb[0].z); v.w = f2tf32(rb[0].w);
        *(uint4*)(pb + brow * BSTR + ac4 * 4) = v;
        if (bpred2) {
            v.x = f2tf32(rb[1].x); v.y = f2tf32(rb[1].y); v.z = f2tf32(rb[1].z); v.w = f2tf32(rb[1].w);
            *(uint4*)(pb + brow2 * BSTR + ac4 * 4) = v;
        }
    };

    ldg(0);
    sts(0);
    __syncthreads();

    const int NKT = HH / GBK;   // 48
    for (int kt = 0; kt < NKT; kt++) {
        int buf = kt & 1;
        if (kt < NKT - 1) ldg(kt + 1);

        const uint32_t* pa = smA + buf * (GBM * ASTR);
        const uint32_t* pb = smB + buf * (GBN * BSTR);
#pragma unroll
        for (int kk = 0; kk < 2; kk++) {
            const int kof = kk * 8;
            uint32_t af[2][4], bf[6][2];
#pragma unroll
            for (int i = 0; i < 2; i++) {
                int m = wm * 32 + i * 16 + r;
                af[i][0] = pa[m * ASTR + kof + cl];
                af[i][1] = pa[(m + 8) * ASTR + kof + cl];
                af[i][2] = pa[m * ASTR + kof + cl + 4];
                af[i][3] = pa[(m + 8) * ASTR + kof + cl + 4];
            }
#pragma unroll
            for (int j = 0; j < 6; j++) {
                int n = wn * 48 + j * 8 + r;
                bf[j][0] = pb[n * BSTR + kof + cl];
                bf[j][1] = pb[n * BSTR + kof + cl + 4];
            }
#pragma unroll
            for (int i = 0; i < 2; i++)
#pragma unroll
                for (int j = 0; j < 6; j++) {
                    asm volatile(
                        "mma.sync.aligned.m16n8k8.row.col.f32.tf32.tf32.f32 "
                        "{%0,%1,%2,%3}, {%4,%5,%6,%7}, {%8,%9}, {%0,%1,%2,%3};"
                        : "+f"(acc[i][j][0]), "+f"(acc[i][j][1]),
                          "+f"(acc[i][j][2]), "+f"(acc[i][j][3])
                        : "r"(af[i][0]), "r"(af[i][1]), "r"(af[i][2]), "r"(af[i][3]),
                          "r"(bf[j][0]), "r"(bf[j][1]));
                }
        }
        if (kt < NKT - 1) {
            sts(buf ^ 1);
            __syncthreads();
        }
    }

    __syncthreads();
#pragma unroll
    for (int i = 0; i < 2; i++)
#pragma unroll
        for (int j = 0; j < 6; j++) {
            int m = wm * 32 + i * 16 + r;
            int n = wn * 48 + j * 8 + 2 * cl;
            gsm[n * GSTR + m]           = acc[i][j][0];
            gsm[(n + 1) * GSTR + m]     = acc[i][j][1];
            gsm[n * GSTR + m + 8]       = acc[i][j][2];
            gsm[(n + 1) * GSTR + m + 8] = acc[i][j][3];
        }
    __syncthreads();

    const int m = tid & 127;
    const int b = m0 + m;
    const float4 x = *(const float4*)(bp + (size_t)b * BP_BSTRIDE);  // t=0
    float hpart = 0.0f;
#pragma unroll
    for (int it = 0; it < 16; it++) {
        int hl = (tid >> 7) + it * 2;
        int hg = hblk * GBH + hl;
        int ri = hg, rg = 2 * HH + hg, ro = 3 * HH + hg;
        float4 wi = ((const float4*)wih)[ri];
        float4 wg = ((const float4*)wih)[rg];
        float4 wo = ((const float4*)wih)[ro];
        float gi = gsm[hl * GSTR + m]        + bih[ri] + bhh[ri]
                 + x.x * wi.x + x.y * wi.y + x.z * wi.z + x.w * wi.w;
        float gg = gsm[(hl + 32) * GSTR + m] + bih[rg] + bhh[rg]
                 + x.x * wg.x + x.y * wg.y + x.z * wg.z + x.w * wg.w;
        float go = gsm[(hl + 64) * GSTR + m] + bih[ro] + bhh[ro]
                 + x.x * wo.x + x.y * wo.y + x.z * wo.z + x.w * wo.w;
        float cn = fast_sigmoid(gi) * fast_tanh(gg);   // c_prev = 0, f-gate dead
        d_ct[(size_t)hg * BB + b] = cn;
        hpart += fast_sigmoid(go) * fast_tanh(cn);
    }
    float v = blockReduce256(hpart);
    if (tid == 0) atomicAdd(&d_hsum[0], v);
}

// ---------------- the single fused persistent kernel ----------------
__global__ __launch_bounds__(256, 2) void fused_kernel(
        const float* __restrict__ bp,  const float* __restrict__ be,
        const float* __restrict__ wih, const float* __restrict__ whh,
        const float* __restrict__ bih, const float* __restrict__ bhh,
        const float* __restrict__ fcw, const float* __restrict__ fcb,
        float* __restrict__ out) {
    extern __shared__ uint32_t sm_u[];
    __shared__ float s_ev[TT];
    __shared__ float s_fc[BB];

    const int tid  = threadIdx.x;
    const int bid  = blockIdx.x;
    const int lane = tid & 31;
    unsigned epoch = 0;

    // zero block-local accumulators (before any phase)
    for (int i = tid; i < BB; i += 256) s_fc[i] = 0.0f;
    if (tid < TT) s_ev[tid] = 0.0f;
    // out = fc_b (block 0); all out-adds happen after later barriers
    if (bid == 0) {
        float fb = fcb[0];
        for (int i = tid; i < BB; i += 256) out[i] = fb;
    }
    __syncthreads();

    // ---- phase G: step-0 GEMM (192 tiles; blocks 192..295 skip to prep) ----
    if (bid < 192) {
        gemm_tile(bid % 24, bid / 24, be, whh, bp, wih, bih, bhh, sm_u);
    }

    // ---- phase A+B (work-stolen): rowsums / biassums / evsums ----
    for (;;) {
        int base;
        if (lane == 0) base = (int)atomicAdd(&d_pctr, 4u);
        base = __shfl_sync(0xffffffffu, base, 0);
        if (base >= NPREP) break;
        int lim = base + 4; if (lim > NPREP) lim = NPREP;
        for (int it = base; it < lim; it++) {
            if (it < NRS) {
                int j = G4 + it;                      // gate row, t>=1
                const float4* p = (const float4*)(whh + (size_t)j * HH);
                float4 a[6];
#pragma unroll
                for (int i = 0; i < 6; i++) a[i] = p[lane + 32 * i];
                float s = warpsum(sum6f4(a));
                if (lane == 0) {
                    d_rowsum[j]  = s;
                    d_biassum[j] = bih[j] + bhh[j];
                }
            } else {
                int rr = it - NRS;
                int t = 1 + (rr >> 10), b = rr & (BB - 1);
                const float4* p = (const float4*)(be + (size_t)b * BE_BSTRIDE + t * HH);
                float4 a[6];
#pragma unroll
                for (int i = 0; i < 6; i++) a[i] = p[lane + 32 * i];
                float s = warpsum(sum6f4(a));
                if (lane == 0) atomicAdd(&s_ev[t], s);
            }
        }
    }
    __syncthreads();
    if (tid < 19) {
        float v = s_ev[tid + 1];
        if (v != 0.0f) atomicAdd(&d_evsum[tid + 1], v);
    }

    gridbar(++epoch * NBLK);

    // ---- phase C: 19 recurrent steps; unit = (h, half-of-batch) ----
    const float4* wih4 = (const float4*)wih;

    for (int t = 1; t < TT; t++) {
        const float hx = d_evsum[t] + d_hsum[t - 1];
        const int last = (t == TT - 1);
        float hacc = 0.0f;

        // preload x for all 4 quarter-batches this thread may touch
        float4 xq[4];
#pragma unroll
        for (int k = 0; k < 4; k++)
            xq[k] = *(const float4*)(bp + (size_t)(tid + (k << 8)) * BP_BSTRIDE + t * DIN);

        const int base = t * G4;
        for (int u = bid; u < 2 * HH; u += NBLK) {
            const int h    = u >> 1;
            const int half = u & 1;
            float4 x0, x1;
            if (half) { x0 = xq[2]; x1 = xq[3]; }
            else      { x0 = xq[0]; x1 = xq[1]; }

            float4 w0 = wih4[base + h];
            float4 w1 = wih4[base + HH + h];
            float4 w2 = wih4[base + 2 * HH + h];
            float4 w3 = wih4[base + 3 * HH + h];
            float pre0 = fmaf(hx, d_rowsum[base + h],          d_biassum[base + h]);
            float pre1 = fmaf(hx, d_rowsum[base + HH + h],     d_biassum[base + HH + h]);
            float pre2 = fmaf(hx, d_rowsum[base + 2 * HH + h], d_biassum[base + 2 * HH + h]);
            float pre3 = fmaf(hx, d_rowsum[base + 3 * HH + h], d_biassum[base + 3 * HH + h]);
            float fw = last ? fcw[h] : 0.0f;
            float* crow = d_ct + (size_t)h * BB + (half << 9);

            {   // k = 0 : b = half*512 + tid
                float gi = pre0 + x0.x * w0.x + x0.y * w0.y + x0.z * w0.z + x0.w * w0.w;
                float gf = pre1 + x0.x * w1.x + x0.y * w1.y + x0.z * w1.z + x0.w * w1.w;
                float gg = pre2 + x0.x * w2.x + x0.y * w2.y + x0.z * w2.z + x0.w * w2.w;
                float go = pre3 + x0.x * w3.x + x0.y * w3.y + x0.z * w3.z + x0.w * w3.w;
                float c  = crow[tid];
                float cn = fast_sigmoid(gf) * c + fast_sigmoid(gi) * fast_tanh(gg);
                crow[tid] = cn;
                float hn = fast_sigmoid(go) * fast_tanh(cn);
                if (last) s_fc[(half << 9) + tid] += hn * fw;
                else      hacc += hn;
            }
            {   // k = 1 : b = half*512 + 256 + tid
                float gi = pre0 + x1.x * w0.x + x1.y * w0.y + x1.z * w0.z + x1.w * w0.w;
                float gf = pre1 + x1.x * w1.x + x1.y * w1.y + x1.z * w1.z + x1.w * w1.w;
                float gg = pre2 + x1.x * w2.x + x1.y * w2.y + x1.z * w2.z + x1.w * w2.w;
                float go = pre3 + x1.x * w3.x + x1.y * w3.y + x1.z * w3.z + x1.w * w3.w;
                float c  = crow[tid + 256];
                float cn = fast_sigmoid(gf) * c + fast_sigmoid(gi) * fast_tanh(gg);
                crow[tid + 256] = cn;
                float hn = fast_sigmoid(go) * fast_tanh(cn);
                if (last) s_fc[(half << 9) + 256 + tid] += hn * fw;
                else      hacc += hn;
            }
        }
        if (!last) {
            float v = blockReduce256(hacc);
            if (tid == 0) atomicAdd(&d_hsum[t], v);
            gridbar(++epoch * NBLK);
        }
    }

    // ---- final FC flush (zero-skip) ----
    __syncthreads();
    for (int i = tid; i < BB; i += 256) {
        float v = s_fc[i];
        if (v != 0.0f) atomicAdd(&out[i], v);
    }

    // ---- end-of-launch self-reset (last finishing block) ----
    __syncthreads();
    if (tid == 0) {
        __threadfence();
        unsigned v = atomicAdd(&d_done, 1u);
        if (v == NBLK - 1) {
            d_barcnt = 0u;
            d_pctr   = 0u;
            d_done   = 0u;
#pragma unroll
            for (int i = 0; i < TT; i++) { d_evsum[i] = 0.0f; d_hsum[i] = 0.0f; }
            __threadfence();
        }
    }
}

// ---------------- launcher ----------------
extern "C" void kernel_launch(void* const* d_in, const int* in_sizes, int n_in,
                              void* d_out, int out_size) {
    const float* bp  = (const float*)d_in[0];
    const float* be  = (const float*)d_in[1];
    const float* wih = (const float*)d_in[2];
    const float* whh = (const float*)d_in[3];
    const float* bih = (const float*)d_in[4];
    const float* bhh = (const float*)d_in[5];
    const float* fcw = (const float*)d_in[6];
    const float* fcb = (const float*)d_in[7];
    float* out = (float*)d_out;

    cudaFuncSetAttribute(fused_kernel,
                         cudaFuncAttributeMaxDynamicSharedMemorySize, FUSED_SMEM);

    fused_kernel<<<NBLK, 256, FUSED_SMEM>>>(bp, be, wih, whh, bih, bhh, fcw, fcb, out);
}